// round 12
// baseline (speedup 1.0000x reference)
#include <cuda_runtime.h>
#include <math_constants.h>

// RandomFeatures, round 12: r9 scalar carry-window core (NQ=4) +
// software-pipelined unit fetch + 2x-unrolled window step (halved shift MOVs),
// 14 warps x 2 CTAs/SM (reg headroom for the bigger window).
// lane = batch; xs transposed [(HALO+T+HALO)][33] in shared; warp-uniform row
// index => conflict-free. Fence-free combine via acq_rel atomic + L2 scratch.

#define MAX_KLEN 11
#define WARPS_PER_CTA 14
#define XPITCH 33
#define HALO 128
#define NQ 4
#define BGMAX 4
#define KMAX 8192

__device__ int   g_ctr[BGMAX];                   // work counter (self-reset)
__device__ int   g_done[BGMAX];                  // CTA done counter (self-reset)
__device__ int   g_arr[BGMAX * KMAX];            // per-k arrivals (self-reset)
__device__ float g_scr[(size_t)BGMAX * KMAX * NQ * 64];

__device__ __forceinline__ int atom_add_acq_rel(int* ptr, int v) {
    int old;
    asm volatile("atom.global.add.acq_rel.gpu.s32 %0, [%1], %2;"
                 : "=r"(old) : "l"(ptr), "r"(v) : "memory");
    return old;
}

// Single 8/4/2/1 step: load NB new values into Y[KLEN-1..], compute NB, shift.
template<int KLEN, int NB>
__device__ __forceinline__ const float* step(
    float* __restrict__ Y,           // window [KLEN-1+16]
    const float* __restrict__ p, int dp,
    const float* __restrict__ w, float bs,
    float& mx, int& ic)
{
#pragma unroll
    for (int t = 0; t < NB; t++) Y[KLEN - 1 + t] = p[t * dp];
#pragma unroll
    for (int i = 0; i < NB; i++) {
        float a = bs;
#pragma unroll
        for (int j = 0; j < KLEN; j++) a = fmaf(w[j], Y[i + j], a);
        mx = fmaxf(mx, a);
        ic += (a > 0.0f) ? 1 : 0;
    }
#pragma unroll
    for (int t = 0; t < KLEN - 1; t++) Y[t] = Y[NB + t];
    return p + NB * dp;
}

// Double step: 16 outputs with a single end-shift (half the MOV traffic).
template<int KLEN>
__device__ __forceinline__ const float* step16(
    float* __restrict__ Y,           // window [KLEN-1+16]
    const float* __restrict__ p, int dp,
    const float* __restrict__ w, float bs,
    float& mx, int& ic)
{
#pragma unroll
    for (int t = 0; t < 16; t++) Y[KLEN - 1 + t] = p[t * dp];
#pragma unroll
    for (int i = 0; i < 16; i++) {
        float a = bs;
#pragma unroll
        for (int j = 0; j < KLEN; j++) a = fmaf(w[j], Y[i + j], a);
        mx = fmaxf(mx, a);
        ic += (a > 0.0f) ? 1 : 0;
    }
#pragma unroll
    for (int t = 0; t < KLEN - 1; t++) Y[t] = Y[16 + t];
    return p + 16 * dp;
}

template<int KLEN>
__device__ __forceinline__ void conv_range(
    const float* __restrict__ xsl,   // xs + lane
    int r, int pd, int mlo, int mhi, int d, int dp,
    const float* __restrict__ w, float bs,
    float& mx, int& ic)
{
    int n = mhi - mlo;
    if (n <= 0) return;
    const float* p = xsl + (HALO + r - pd + mlo * d) * XPITCH;
    float Y[KLEN - 1 + 16];
#pragma unroll
    for (int t = 0; t < KLEN - 1; t++) Y[t] = p[t * dp];    // prologue window
    p += (KLEN - 1) * dp;
    while (n >= 16) { p = step16<KLEN>(Y, p, dp, w, bs, mx, ic); n -= 16; }
    if (n & 8) p = step<KLEN, 8>(Y, p, dp, w, bs, mx, ic);
    if (n & 4) p = step<KLEN, 4>(Y, p, dp, w, bs, mx, ic);
    if (n & 2) p = step<KLEN, 2>(Y, p, dp, w, bs, mx, ic);
    if (n & 1)     step<KLEN, 1>(Y, p, dp, w, bs, mx, ic);
}

template<int KLEN>
__device__ __forceinline__ void process_unit(
    const float* __restrict__ xsl, int d, int pd, int ol, int q,
    const float* __restrict__ w, float bs, float& mx, int& ic)
{
    const int dp = d * XPITCH;
    const int q0 = (ol - 1) / d;                 // one division per unit
    const int rr = (ol - 1) - q0 * d;
    if (d >= NQ) {
        for (int r = q; r < d; r += NQ) {
            const int M = (r <= rr) ? q0 + 1 : q0;   // = ceil((ol-r)/d)
            conv_range<KLEN>(xsl, r, pd, 0, M, d, dp, w, bs, mx, ic);
        }
    } else {
        for (int r = 0; r < d; r++) {
            const int M = (r <= rr) ? q0 + 1 : q0;
            conv_range<KLEN>(xsl, r, pd, (q * M) >> 2, ((q + 1) * M) >> 2,
                             d, dp, w, bs, mx, ic);
        }
    }
}

// Cold safe fallback for parameters outside the halo guarantee (not expected).
template<int KLEN>
__device__ __forceinline__ void process_unit_safe(
    const float* __restrict__ xsl, int d, int pd, int ol, int q, int T,
    const float* __restrict__ w, float bs, float& mx, int& ic)
{
    const int lo = (q * ol) >> 2, hi = ((q + 1) * ol) >> 2;
    for (int p = lo; p < hi; p++) {
        float a = bs;
#pragma unroll
        for (int j = 0; j < KLEN; j++) {
            const long long ix = (long long)p - pd + (long long)j * d;
            const int ixc = (int)min(max(ix, 0LL), (long long)(T - 1));
            float v = xsl[(HALO + ixc) * XPITCH];
            a = fmaf(w[j], (ix >= 0 && ix < T) ? v : 0.0f, a);
        }
        mx = fmaxf(mx, a);
        ic += (a > 0.0f) ? 1 : 0;
    }
}

__global__ void __launch_bounds__(32 * WARPS_PER_CTA, 2)
rf_main(const float* __restrict__ x,
        const float* __restrict__ w,
        const float* __restrict__ bias,
        const int*   __restrict__ dil,
        const int*   __restrict__ padr,
        const int*   __restrict__ olen,
        float* __restrict__ out,
        int B, int T, int K)
{
    extern __shared__ float xs[];                 // [(HALO+T+HALO)][XPITCH]
    const int lane = threadIdx.x & 31;
    const int warp = threadIdx.x >> 5;
    const int bg   = blockIdx.y;
    const int b0   = bg * 32;
    const int nb   = min(32, B - b0);

    // Transposed fill with zero halos: coalesced LDG, conflict-free STS (33 odd).
    for (int bb = warp; bb < 32; bb += WARPS_PER_CTA) {
        const int bsafe = min(bb, nb - 1);
        for (int t = lane; t < HALO; t += 32) {
            xs[t * XPITCH + bb] = 0.0f;
            xs[(HALO + T + t) * XPITCH + bb] = 0.0f;
        }
        for (int t = lane; t < T; t += 32) {
            float v = x[(size_t)(b0 + bsafe) * T + t];
            xs[(HALO + t) * XPITCH + bb] = (bb < nb) ? v : 0.0f;
        }
    }
    __syncthreads();

    const float* xsl = xs + lane;
    const int nunits = K * NQ;

    // Software-pipelined unit fetch: next unit's atomic in flight during work.
    int u = 0;
    if (lane == 0) u = atomicAdd(&g_ctr[bg], 1);
    u = __shfl_sync(0xFFFFFFFFu, u, 0);

    while (u < nunits) {
        int unext = 0;
        if (lane == 0) unext = atomicAdd(&g_ctr[bg], 1);

        const int k = u >> 2;
        const int q = u & (NQ - 1);
        const int   d  = dil[k];
        const int   pd = padr[k];
        const int   ol = olen[k];
        const float bv = bias[k];

        float wreg[MAX_KLEN];
#pragma unroll
        for (int j = 0; j < MAX_KLEN; j++)
            wreg[j] = __ldg(&w[(size_t)k * MAX_KLEN + j]);

        float mx = -CUDART_INF_F;
        int   ic = 0;

        // klen inference: taps >= klen are exactly zero by construction.
        const int klen = (wreg[9] != 0.0f || wreg[10] != 0.0f) ? 11
                       : (wreg[7] != 0.0f || wreg[8] != 0.0f) ? 9 : 7;
        const bool safe = (d >= 1) && (pd < HALO) &&
                          ((ol - 1) - pd + (long long)(klen - 1) * d < T + HALO);

        if (safe) {
            if (klen == 11)      process_unit<11>(xsl, d, pd, ol, q, wreg, bv, mx, ic);
            else if (klen == 9)  process_unit<9>(xsl, d, pd, ol, q, wreg, bv, mx, ic);
            else                 process_unit<7>(xsl, d, pd, ol, q, wreg, bv, mx, ic);
        } else if (d >= 1) {
            if (klen == 11)      process_unit_safe<11>(xsl, d, pd, ol, q, T, wreg, bv, mx, ic);
            else if (klen == 9)  process_unit_safe<9>(xsl, d, pd, ol, q, T, wreg, bv, mx, ic);
            else                 process_unit_safe<7>(xsl, d, pd, ol, q, T, wreg, bv, mx, ic);
        }

        // Publish partial via L2 (no L1 copies -> no stale reads, no fences).
        float* s = g_scr + (((size_t)bg * KMAX + k) * NQ + q) * 64;
        __stcg(&s[lane], mx);
        __stcg(&s[32 + lane], (float)ic);
        // acq_rel arrival: releases our stores, acquires others' on the winner.
        int arrived = 0;
        if (lane == 0) arrived = atom_add_acq_rel(&g_arr[bg * KMAX + k], 1);
        arrived = __shfl_sync(0xFFFFFFFFu, arrived, 0);
        if (arrived == NQ - 1) {
            const float* sb = g_scr + (((size_t)bg * KMAX + k) * NQ) * 64;
            float M = __ldcg(&sb[lane]), C = __ldcg(&sb[32 + lane]);
#pragma unroll
            for (int q2 = 1; q2 < NQ; q2++) {
                M  = fmaxf(M, __ldcg(&sb[q2 * 64 + lane]));
                C += __ldcg(&sb[q2 * 64 + 32 + lane]);
            }
            if (lane < nb) {
                float* o = out + (size_t)(b0 + lane) * 2 * K + 2 * k;
                o[0] = M;
                o[1] = C / (float)ol;
            }
            if (lane == 0) g_arr[bg * KMAX + k] = 0;   // self-reset for replay
        }

        u = __shfl_sync(0xFFFFFFFFu, unext, 0);
    }

    // Last CTA per batch group resets the work counter for the next replay.
    __syncthreads();
    if (threadIdx.x == 0) {
        int dn = atomicAdd(&g_done[bg], 1);
        if (dn == (int)gridDim.x - 1) {
            g_ctr[bg]  = 0;
            g_done[bg] = 0;
        }
    }
}

extern "C" void kernel_launch(void* const* d_in, const int* in_sizes, int n_in,
                              void* d_out, int out_size) {
    const float* x    = (const float*)d_in[0];
    const float* w    = (const float*)d_in[1];
    const float* bias = (const float*)d_in[2];
    const int*   dil  = (const int*)d_in[3];
    const int*   padr = (const int*)d_in[4];
    const int*   olen = (const int*)d_in[5];
    float* out = (float*)d_out;

    const int K = in_sizes[2];                 // bias element count
    const int B = out_size / (2 * K);
    const int T = in_sizes[0] / B;
    const int nbg = (B + 31) / 32;             // batch groups (<= BGMAX)

    const size_t smem = (size_t)(2 * HALO + T) * XPITCH * sizeof(float);
    cudaFuncSetAttribute(rf_main,
                         cudaFuncAttributeMaxDynamicSharedMemorySize,
                         (int)smem);

    // 2 CTAs/SM x 148 SMs persistent, split across batch groups.
    int ctas_per_bg = (296 + nbg - 1) / nbg;
    dim3 grid(ctas_per_bg, nbg);
    rf_main<<<grid, 32 * WARPS_PER_CTA, smem>>>(x, w, bias, dil, padr, olen,
                                                out, B, T, K);
}

// round 13
// speedup vs baseline: 1.9440x; 1.9440x over previous
#include <cuda_runtime.h>
#include <math_constants.h>

// RandomFeatures, round 13: r9 champion (carry-window, NQ=4, L2 scratch,
// acq_rel combine, 15 warps x 2 CTAs) + ONE change: software-pipelined unit
// fetch (next unit's atomicAdd issued before current unit's compute).
// lane = batch; xs transposed [(HALO+T+HALO)][33] in shared; warp-uniform row
// index => conflict-free.

#define MAX_KLEN 11
#define WARPS_PER_CTA 15
#define XPITCH 33
#define HALO 128
#define NQ 4
#define BGMAX 4
#define KMAX 8192

__device__ int   g_ctr[BGMAX];                   // work counter (self-reset)
__device__ int   g_done[BGMAX];                  // CTA done counter (self-reset)
__device__ int   g_arr[BGMAX * KMAX];            // per-k arrivals (self-reset)
__device__ float g_scr[(size_t)BGMAX * KMAX * NQ * 64];

__device__ __forceinline__ int atom_add_acq_rel(int* ptr, int v) {
    int old;
    asm volatile("atom.global.add.acq_rel.gpu.s32 %0, [%1], %2;"
                 : "=r"(old) : "l"(ptr), "r"(v) : "memory");
    return old;
}

// One carry-window step: load NB new values, compute NB outputs, shift window.
template<int KLEN, int NB>
__device__ __forceinline__ const float* step(
    float* __restrict__ Y,           // window [KLEN-1+8]
    const float* __restrict__ p, int dp,
    const float* __restrict__ w, float bs,
    float& mx, int& ic)
{
#pragma unroll
    for (int t = 0; t < NB; t++) Y[KLEN - 1 + t] = p[t * dp];
#pragma unroll
    for (int i = 0; i < NB; i++) {
        float a = bs;
#pragma unroll
        for (int j = 0; j < KLEN; j++) a = fmaf(w[j], Y[i + j], a);
        mx = fmaxf(mx, a);              // FMNMX: alu pipe
        ic += (a > 0.0f) ? 1 : 0;       // FSETP + pred IADD
    }
#pragma unroll
    for (int t = 0; t < KLEN - 1; t++) Y[t] = Y[NB + t];
    return p + NB * dp;
}

template<int KLEN>
__device__ __forceinline__ void conv_range(
    const float* __restrict__ xsl,   // xs + lane
    int r, int pd, int mlo, int mhi, int d, int dp,
    const float* __restrict__ w, float bs,
    float& mx, int& ic)
{
    int n = mhi - mlo;
    if (n <= 0) return;
    const float* p = xsl + (HALO + r - pd + mlo * d) * XPITCH;
    float Y[KLEN - 1 + 8];
#pragma unroll
    for (int t = 0; t < KLEN - 1; t++) Y[t] = p[t * dp];    // prologue window
    p += (KLEN - 1) * dp;
    while (n >= 8) { p = step<KLEN, 8>(Y, p, dp, w, bs, mx, ic); n -= 8; }
    if (n & 4) p = step<KLEN, 4>(Y, p, dp, w, bs, mx, ic);
    if (n & 2) p = step<KLEN, 2>(Y, p, dp, w, bs, mx, ic);
    if (n & 1)     step<KLEN, 1>(Y, p, dp, w, bs, mx, ic);
}

template<int KLEN>
__device__ __forceinline__ void process_unit(
    const float* __restrict__ xsl, int d, int pd, int ol, int q,
    const float* __restrict__ w, float bs, float& mx, int& ic)
{
    const int dp = d * XPITCH;
    const int q0 = (ol - 1) / d;                 // one division per unit
    const int rr = (ol - 1) - q0 * d;
    if (d >= NQ) {
        for (int r = q; r < d; r += NQ) {
            const int M = (r <= rr) ? q0 + 1 : q0;   // = ceil((ol-r)/d)
            conv_range<KLEN>(xsl, r, pd, 0, M, d, dp, w, bs, mx, ic);
        }
    } else {
        for (int r = 0; r < d; r++) {
            const int M = (r <= rr) ? q0 + 1 : q0;
            conv_range<KLEN>(xsl, r, pd, (q * M) >> 2, ((q + 1) * M) >> 2,
                             d, dp, w, bs, mx, ic);
        }
    }
}

// Cold safe fallback for parameters outside the halo guarantee (not expected).
template<int KLEN>
__device__ __forceinline__ void process_unit_safe(
    const float* __restrict__ xsl, int d, int pd, int ol, int q, int T,
    const float* __restrict__ w, float bs, float& mx, int& ic)
{
    const int lo = (q * ol) >> 2, hi = ((q + 1) * ol) >> 2;
    for (int p = lo; p < hi; p++) {
        float a = bs;
#pragma unroll
        for (int j = 0; j < KLEN; j++) {
            const long long ix = (long long)p - pd + (long long)j * d;
            const int ixc = (int)min(max(ix, 0LL), (long long)(T - 1));
            float v = xsl[(HALO + ixc) * XPITCH];
            a = fmaf(w[j], (ix >= 0 && ix < T) ? v : 0.0f, a);
        }
        mx = fmaxf(mx, a);
        ic += (a > 0.0f) ? 1 : 0;
    }
}

__global__ void __launch_bounds__(32 * WARPS_PER_CTA, 2)
rf_main(const float* __restrict__ x,
        const float* __restrict__ w,
        const float* __restrict__ bias,
        const int*   __restrict__ dil,
        const int*   __restrict__ padr,
        const int*   __restrict__ olen,
        float* __restrict__ out,
        int B, int T, int K)
{
    extern __shared__ float xs[];                 // [(HALO+T+HALO)][XPITCH]
    const int lane = threadIdx.x & 31;
    const int warp = threadIdx.x >> 5;
    const int bg   = blockIdx.y;
    const int b0   = bg * 32;
    const int nb   = min(32, B - b0);

    // Transposed fill with zero halos: coalesced LDG, conflict-free STS (33 odd).
    for (int bb = warp; bb < 32; bb += WARPS_PER_CTA) {
        const int bsafe = min(bb, nb - 1);
        for (int t = lane; t < HALO; t += 32) {
            xs[t * XPITCH + bb] = 0.0f;
            xs[(HALO + T + t) * XPITCH + bb] = 0.0f;
        }
        for (int t = lane; t < T; t += 32) {
            float v = x[(size_t)(b0 + bsafe) * T + t];
            xs[(HALO + t) * XPITCH + bb] = (bb < nb) ? v : 0.0f;
        }
    }
    __syncthreads();

    const float* xsl = xs + lane;
    const int nunits = K * NQ;

    // Software-pipelined unit fetch: next unit's atomic in flight during work.
    int u = 0;
    if (lane == 0) u = atomicAdd(&g_ctr[bg], 1);
    u = __shfl_sync(0xFFFFFFFFu, u, 0);

    while (u < nunits) {
        int unext = 0;
        if (lane == 0) unext = atomicAdd(&g_ctr[bg], 1);   // hidden behind compute

        const int k = u >> 2;
        const int q = u & (NQ - 1);
        const int   d  = dil[k];
        const int   pd = padr[k];
        const int   ol = olen[k];
        const float bv = bias[k];

        float wreg[MAX_KLEN];
#pragma unroll
        for (int j = 0; j < MAX_KLEN; j++)
            wreg[j] = __ldg(&w[(size_t)k * MAX_KLEN + j]);

        float mx = -CUDART_INF_F;
        int   ic = 0;

        // klen inference: taps >= klen are exactly zero by construction.
        const int klen = (wreg[9] != 0.0f || wreg[10] != 0.0f) ? 11
                       : (wreg[7] != 0.0f || wreg[8] != 0.0f) ? 9 : 7;
        const bool safe = (d >= 1) && (pd < HALO) &&
                          ((ol - 1) - pd + (long long)(klen - 1) * d < T + HALO);

        if (safe) {
            if (klen == 11)      process_unit<11>(xsl, d, pd, ol, q, wreg, bv, mx, ic);
            else if (klen == 9)  process_unit<9>(xsl, d, pd, ol, q, wreg, bv, mx, ic);
            else                 process_unit<7>(xsl, d, pd, ol, q, wreg, bv, mx, ic);
        } else if (d >= 1) {
            if (klen == 11)      process_unit_safe<11>(xsl, d, pd, ol, q, T, wreg, bv, mx, ic);
            else if (klen == 9)  process_unit_safe<9>(xsl, d, pd, ol, q, T, wreg, bv, mx, ic);
            else                 process_unit_safe<7>(xsl, d, pd, ol, q, T, wreg, bv, mx, ic);
        }

        // Publish partial via L2 (no L1 copies -> no stale reads, no fences).
        float* s = g_scr + (((size_t)bg * KMAX + k) * NQ + q) * 64;
        __stcg(&s[lane], mx);
        __stcg(&s[32 + lane], (float)ic);
        // acq_rel arrival: releases our stores, acquires others' on the winner.
        int arrived = 0;
        if (lane == 0) arrived = atom_add_acq_rel(&g_arr[bg * KMAX + k], 1);
        arrived = __shfl_sync(0xFFFFFFFFu, arrived, 0);
        if (arrived == NQ - 1) {
            const float* sb = g_scr + (((size_t)bg * KMAX + k) * NQ) * 64;
            float M = __ldcg(&sb[lane]), C = __ldcg(&sb[32 + lane]);
#pragma unroll
            for (int q2 = 1; q2 < NQ; q2++) {
                M  = fmaxf(M, __ldcg(&sb[q2 * 64 + lane]));
                C += __ldcg(&sb[q2 * 64 + 32 + lane]);
            }
            if (lane < nb) {
                float* o = out + (size_t)(b0 + lane) * 2 * K + 2 * k;
                o[0] = M;
                o[1] = C / (float)ol;
            }
            if (lane == 0) g_arr[bg * KMAX + k] = 0;   // self-reset for replay
        }

        u = __shfl_sync(0xFFFFFFFFu, unext, 0);
    }

    // Last CTA per batch group resets the work counter for the next replay.
    __syncthreads();
    if (threadIdx.x == 0) {
        int dn = atomicAdd(&g_done[bg], 1);
        if (dn == (int)gridDim.x - 1) {
            g_ctr[bg]  = 0;
            g_done[bg] = 0;
        }
    }
}

extern "C" void kernel_launch(void* const* d_in, const int* in_sizes, int n_in,
                              void* d_out, int out_size) {
    const float* x    = (const float*)d_in[0];
    const float* w    = (const float*)d_in[1];
    const float* bias = (const float*)d_in[2];
    const int*   dil  = (const int*)d_in[3];
    const int*   padr = (const int*)d_in[4];
    const int*   olen = (const int*)d_in[5];
    float* out = (float*)d_out;

    const int K = in_sizes[2];                 // bias element count
    const int B = out_size / (2 * K);
    const int T = in_sizes[0] / B;
    const int nbg = (B + 31) / 32;             // batch groups (<= BGMAX)

    const size_t smem = (size_t)(2 * HALO + T) * XPITCH * sizeof(float);
    cudaFuncSetAttribute(rf_main,
                         cudaFuncAttributeMaxDynamicSharedMemorySize,
                         (int)smem);

    // 2 CTAs/SM x 148 SMs persistent, split across batch groups.
    int ctas_per_bg = (296 + nbg - 1) / nbg;
    dim3 grid(ctas_per_bg, nbg);
    rf_main<<<grid, 32 * WARPS_PER_CTA, smem>>>(x, w, bias, dil, padr, olen,
                                                out, B, T, K);
}

// round 14
// speedup vs baseline: 2.1057x; 1.0832x over previous
#include <cuda_runtime.h>
#include <math_constants.h>

// RandomFeatures, round 14: exact r6 main (champion, ~43us) + fast rf_fin
// (4 k's per thread, 32 independent L2 loads in flight -> latency hidden).
// lane = batch; xs transposed [(HALO+T+HALO)][33] in shared; warp-uniform row
// index => bank = lane => conflict-free. Sliding-window register reuse per
// residue class; exact 8/4/2/1 block chain; dynamic quarter-units via atomic.

#define MAX_KLEN 11
#define WARPS_PER_CTA 15
#define XPITCH 33
#define HALO 128
#define NQ 4
#define BGMAX 4
#define KMAX 8192

__device__ int   g_ctr[BGMAX];          // zero-initialized; rf_fin re-zeroes
__device__ float g_scr[(size_t)BGMAX * KMAX * NQ * 64];

template<int KLEN, int NB>
__device__ __forceinline__ void conv_block(
    const float* __restrict__ p,     // &xs[(HALO+base)*XPITCH + lane]
    int dp,                          // d * XPITCH
    const float* __restrict__ w, float bs,
    float& mx, float& cnt)
{
    float Y[NB + KLEN - 1];
#pragma unroll
    for (int t = 0; t < NB + KLEN - 1; t++) Y[t] = p[t * dp];
#pragma unroll
    for (int i = 0; i < NB; i++) {
        float a = bs;
#pragma unroll
        for (int j = 0; j < KLEN; j++) a = fmaf(w[j], Y[i + j], a);
        mx = fmaxf(mx, a);
        cnt += (a > 0.0f) ? 1.0f : 0.0f;
    }
}

template<int KLEN>
__device__ __forceinline__ void conv_range(
    const float* __restrict__ xsl,   // xs + lane
    int r, int pd, int mlo, int mhi, int d, int dp,
    const float* __restrict__ w, float bs,
    float& mx, float& cnt)
{
    int m0 = mlo;
    const float* p = xsl + (HALO + r - pd + m0 * d) * XPITCH;
    for (; m0 + 8 <= mhi; m0 += 8) {
        conv_block<KLEN, 8>(p, dp, w, bs, mx, cnt);
        p += 8 * dp;
    }
    if (m0 + 4 <= mhi) { conv_block<KLEN, 4>(p, dp, w, bs, mx, cnt); m0 += 4; p += 4 * dp; }
    if (m0 + 2 <= mhi) { conv_block<KLEN, 2>(p, dp, w, bs, mx, cnt); m0 += 2; p += 2 * dp; }
    if (m0 < mhi)      { conv_block<KLEN, 1>(p, dp, w, bs, mx, cnt); }
}

template<int KLEN>
__device__ __forceinline__ void process_unit(
    const float* __restrict__ xsl, int d, int pd, int ol, int q,
    const float* __restrict__ w, float bs, float& mx, float& cnt)
{
    const int dp = d * XPITCH;
    const int q0 = (ol - 1) / d;                 // one division per unit
    const int rr = (ol - 1) - q0 * d;
    if (d >= NQ) {
        for (int r = q; r < d; r += NQ) {
            const int M = (r <= rr) ? q0 + 1 : q0;   // = ceil((ol-r)/d)
            conv_range<KLEN>(xsl, r, pd, 0, M, d, dp, w, bs, mx, cnt);
        }
    } else {
        for (int r = 0; r < d; r++) {
            const int M = (r <= rr) ? q0 + 1 : q0;
            conv_range<KLEN>(xsl, r, pd, (q * M) >> 2, ((q + 1) * M) >> 2,
                             d, dp, w, bs, mx, cnt);
        }
    }
}

// Safe fallback for parameters outside the halo guarantee (not expected).
template<int KLEN>
__device__ __forceinline__ void process_unit_safe(
    const float* __restrict__ xsl, int d, int pd, int ol, int q, int T,
    const float* __restrict__ w, float bs, float& mx, float& cnt)
{
    const int lo = (q * ol) >> 2, hi = ((q + 1) * ol) >> 2;
    for (int p = lo; p < hi; p++) {
        float a = bs;
#pragma unroll
        for (int j = 0; j < KLEN; j++) {
            const long long ix = (long long)p - pd + (long long)j * d;
            const int ixc = (int)min(max(ix, 0LL), (long long)(T - 1));
            float v = xsl[(HALO + ixc) * XPITCH];
            a = fmaf(w[j], (ix >= 0 && ix < T) ? v : 0.0f, a);
        }
        mx = fmaxf(mx, a);
        cnt += (a > 0.0f) ? 1.0f : 0.0f;
    }
}

__global__ void __launch_bounds__(32 * WARPS_PER_CTA, 2)
rf_main(const float* __restrict__ x,
        const float* __restrict__ w,
        const float* __restrict__ bias,
        const int*   __restrict__ dil,
        const int*   __restrict__ padr,
        const int*   __restrict__ olen,
        int B, int T, int K)
{
    extern __shared__ float xs[];                 // [(HALO+T+HALO)][XPITCH]
    const int lane = threadIdx.x & 31;
    const int warp = threadIdx.x >> 5;
    const int bg   = blockIdx.y;
    const int b0   = bg * 32;
    const int nb   = min(32, B - b0);

    // Transposed fill with zero halos: coalesced LDG, conflict-free STS (33 odd).
    for (int bb = warp; bb < 32; bb += WARPS_PER_CTA) {
        const int bsafe = min(bb, nb - 1);
        for (int t = lane; t < HALO; t += 32) {
            xs[t * XPITCH + bb] = 0.0f;
            xs[(HALO + T + t) * XPITCH + bb] = 0.0f;
        }
        for (int t = lane; t < T; t += 32) {
            float v = x[(size_t)(b0 + bsafe) * T + t];
            xs[(HALO + t) * XPITCH + bb] = (bb < nb) ? v : 0.0f;
        }
    }
    __syncthreads();

    const float* xsl = xs + lane;
    const int nunits = K * NQ;

    for (;;) {
        int u = 0;
        if (lane == 0) u = atomicAdd(&g_ctr[bg], 1);
        u = __shfl_sync(0xFFFFFFFFu, u, 0);
        if (u >= nunits) break;

        const int k = u >> 2;
        const int q = u & (NQ - 1);
        const int   d  = dil[k];
        const int   pd = padr[k];
        const int   ol = olen[k];
        const float bv = bias[k];

        float wreg[MAX_KLEN];
#pragma unroll
        for (int j = 0; j < MAX_KLEN; j++)
            wreg[j] = __ldg(&w[(size_t)k * MAX_KLEN + j]);

        float mx  = -CUDART_INF_F;
        float cnt = 0.0f;

        // klen inference: taps >= klen are exactly zero by construction.
        const int klen = (wreg[9] != 0.0f || wreg[10] != 0.0f) ? 11
                       : (wreg[7] != 0.0f || wreg[8] != 0.0f) ? 9 : 7;
        const bool safe = (d >= 1) && (pd < HALO) &&
                          ((ol - 1) - pd + (long long)(klen - 1) * d < T + HALO);

        if (safe) {
            if (klen == 11)      process_unit<11>(xsl, d, pd, ol, q, wreg, bv, mx, cnt);
            else if (klen == 9)  process_unit<9>(xsl, d, pd, ol, q, wreg, bv, mx, cnt);
            else                 process_unit<7>(xsl, d, pd, ol, q, wreg, bv, mx, cnt);
        } else if (d >= 1) {
            if (klen == 11)      process_unit_safe<11>(xsl, d, pd, ol, q, T, wreg, bv, mx, cnt);
            else if (klen == 9)  process_unit_safe<9>(xsl, d, pd, ol, q, T, wreg, bv, mx, cnt);
            else                 process_unit_safe<7>(xsl, d, pd, ol, q, T, wreg, bv, mx, cnt);
        }

        float* s = g_scr + ((size_t)bg * KMAX * NQ + u) * 64;
        s[lane]      = mx;
        s[32 + lane] = cnt;
    }
}

// Fast finalize: each thread handles one lane x 4 consecutive k's with all 32
// partial-loads issued up front via __ldcg (L2-direct; rf_main wrote via L1
// but the kernel boundary makes them visible; scratch is L2-resident).
__global__ void rf_fin(const int* __restrict__ olen,
                       float* __restrict__ out, int B, int K)
{
    const int bg = blockIdx.y;
    // Reset the work counter for the next graph replay (runs after rf_main).
    if (blockIdx.x == 0 && threadIdx.x == 0 && threadIdx.y == 0)
        g_ctr[bg] = 0;

    const int lane = threadIdx.x;                 // batch within group
    const int k0   = (blockIdx.x * blockDim.y + threadIdx.y) * 4;
    const int b    = bg * 32 + lane;
    if (k0 >= K || b >= B) return;

    const int nk = min(4, K - k0);
    float M[4], C[4];
#pragma unroll
    for (int i = 0; i < 4; i++) {
        if (i < nk) {
            const float* s = g_scr + ((size_t)bg * KMAX + k0 + i) * NQ * 64;
            float m0 = __ldcg(&s[lane]),            c0 = __ldcg(&s[32 + lane]);
            float m1 = __ldcg(&s[64 + lane]),       c1 = __ldcg(&s[96 + lane]);
            float m2 = __ldcg(&s[128 + lane]),      c2 = __ldcg(&s[160 + lane]);
            float m3 = __ldcg(&s[192 + lane]),      c3 = __ldcg(&s[224 + lane]);
            M[i] = fmaxf(fmaxf(m0, m1), fmaxf(m2, m3));
            C[i] = (c0 + c1) + (c2 + c3);
        }
    }
    float* o = out + (size_t)b * 2 * K + 2 * k0;
#pragma unroll
    for (int i = 0; i < 4; i++) {
        if (i < nk) {
            o[2 * i]     = M[i];
            o[2 * i + 1] = C[i] / (float)olen[k0 + i];
        }
    }
}

extern "C" void kernel_launch(void* const* d_in, const int* in_sizes, int n_in,
                              void* d_out, int out_size) {
    const float* x    = (const float*)d_in[0];
    const float* w    = (const float*)d_in[1];
    const float* bias = (const float*)d_in[2];
    const int*   dil  = (const int*)d_in[3];
    const int*   padr = (const int*)d_in[4];
    const int*   olen = (const int*)d_in[5];
    float* out = (float*)d_out;

    const int K = in_sizes[2];                 // bias element count
    const int B = out_size / (2 * K);
    const int T = in_sizes[0] / B;
    const int nbg = (B + 31) / 32;             // batch groups (<= BGMAX)

    const size_t smem = (size_t)(2 * HALO + T) * XPITCH * sizeof(float);
    cudaFuncSetAttribute(rf_main,
                         cudaFuncAttributeMaxDynamicSharedMemorySize,
                         (int)smem);

    // 2 CTAs/SM x 148 SMs persistent, split across batch groups.
    int ctas_per_bg = (296 + nbg - 1) / nbg;
    dim3 grid(ctas_per_bg, nbg);
    rf_main<<<grid, 32 * WARPS_PER_CTA, smem>>>(x, w, bias, dil, padr, olen,
                                                B, T, K);

    // Finalize: 8 warps/block, each thread = (lane, 4 k's).
    dim3 fblock(32, 8);
    dim3 fgrid((K + 31) / 32, nbg);
    rf_fin<<<fgrid, fblock>>>(olen, out, B, K);
}